// round 6
// baseline (speedup 1.0000x reference)
#include <cuda_runtime.h>
#include <math.h>
#include <stdint.h>

#define NB 2
#define NA 16384
#define NM 32
#define NC 15
#define PI_F 3.14159265358979323846f

typedef long long ll;

#define NEGK (-9223372036854775807ll - 1ll)
#define N4 NEGK, NEGK, NEGK, NEGK
#define N32 N4, N4, N4, N4, N4, N4, N4, N4

// ---------------- persistent scratch (state restored each run) ----------------
__device__ float  g_md[NB][NA][NM];                    // pair entries rewritten each run
__device__ ll     g_rowkey[NB][NA];                    // fully rewritten by k_match
__device__ ll     g_colkeyF[NB][NM];                   // identity 0; reset by finalize
__device__ ll     g_colkeyP[NB][NM] = {{N32}, {N32}};  // identity NEGK; reset by finalize
__device__ int    g_list[NB * NA];                     // interesting anchors
__device__ int    g_listCount;                         // reset by finalize
__device__ double g_cls_sum[NB];                       // reset by finalize
__device__ double g_reg_sum[NB];
__device__ int    g_numpos[NB];
__device__ unsigned g_ticket;                          // reset by finalize

// key = (float_bits(v) << 32) - idx  (v >= 0): max favors larger v, then smaller idx.
__device__ __forceinline__ ll spack(float v, unsigned idx) {
    return (ll)((unsigned long long)__float_as_uint(v) << 32) - (ll)idx;
}
__device__ __forceinline__ void sdec(ll k, float& v, unsigned& idx) {
    unsigned lo = (unsigned)(k & 0xFFFFFFFFll);
    idx = (unsigned)(-(int)lo);
    unsigned vb = (unsigned)(((unsigned long long)(k + (ll)idx)) >> 32);
    v = __uint_as_float(vb);
}

__device__ __forceinline__ float warp_sum_f(float v) {
#pragma unroll
    for (int off = 16; off > 0; off >>= 1) v += __shfl_xor_sync(0xffffffffu, v, off);
    return v;
}

// focal "background" term; used identically in phase A and corrections
__device__ __forceinline__ float baseterm(float xr) {
    float x = fminf(fmaxf(xr, 0.0001f), 1.0f - 0.0001f);
    return 0.75f * x * x * (-__logf(1.0f - x + 1e-6f));
}

// Sutherland-Hodgman on centered f32 coordinates.
__device__ float quad_inter_area_f(const float* ax, const float* ay,
                                   const float* bx, const float* by) {
    float px[10], py[10], qx[10], qy[10];
    int n = 4;
#pragma unroll
    for (int i = 0; i < 4; i++) { px[i] = ax[i]; py[i] = ay[i]; }
    for (int e = 0; e < 4; e++) {
        float x0 = bx[e], y0 = by[e];
        int e2 = (e + 1) & 3;
        float dx = bx[e2] - x0, dy = by[e2] - y0;
        int m = 0;
        float xprev = px[n - 1], yprev = py[n - 1];
        float dprev = dx * (yprev - y0) - dy * (xprev - x0);
        for (int i = 0; i < n; i++) {
            float xc = px[i], yc = py[i];
            float dc = dx * (yc - y0) - dy * (xc - x0);
            bool inc = (dc >= 0.0f), inp = (dprev >= 0.0f);
            if (inc != inp) {
                float t = dprev / (dprev - dc);
                if (m < 10) { qx[m] = xprev + t * (xc - xprev); qy[m] = yprev + t * (yc - yprev); m++; }
            }
            if (inc) { if (m < 10) { qx[m] = xc; qy[m] = yc; m++; } }
            dprev = dc; xprev = xc; yprev = yc;
        }
        n = m;
        if (n == 0) return 0.0f;
        for (int i = 0; i < n; i++) { px[i] = qx[i]; py[i] = qy[i]; }
    }
    if (n < 3) return 0.0f;
    float s = 0.0f;
    float xp = px[n - 1], yp = py[n - 1];
    for (int i = 0; i < n; i++) { s += xp * py[i] - px[i] * yp; xp = px[i]; yp = py[i]; }
    return 0.5f * fabsf(s);
}

// ---------------- 1: match = filter + clip, all block-local ----------------
__global__ void __launch_bounds__(128) k_match(const float* __restrict__ anc,
                                               const float* __restrict__ ranc,
                                               const float* __restrict__ ann) {
    int img = blockIdx.x >> 7;
    int abase = (blockIdx.x & 127) * 128;
    int t = threadIdx.x;
    int lane = t & 31;

    __shared__ float sgx[NM][4], sgy[NM][4], sgar[NM];
    __shared__ float sqx1[NM], sqy1[NM], sqx2[NM], sqy2[NM], sqar[NM];
    __shared__ ll srow[128];
    __shared__ ll scolF[NM];
    __shared__ int slist[4096];
    __shared__ int scount;

    srow[t] = 0;
    if (t < NM) {
        const float* g = ann + (size_t)(img * NM + t) * 6;
        float cx = g[0], cy = g[1], w = g[2], h = g[3];
        float th = g[4] * (PI_F / 180.0f);
        float sn, cs;
        sincosf(th, &sn, &cs);
        const float lx[4] = {-0.5f, 0.5f, 0.5f, -0.5f};
        const float ly[4] = {-0.5f, -0.5f, 0.5f, 0.5f};
#pragma unroll
        for (int k = 0; k < 4; k++) {
            float dx = w * lx[k], dy = h * ly[k];
            sgx[t][k] = cx + dx * cs - dy * sn;
            sgy[t][k] = cy + dx * sn + dy * cs;
        }
        sgar[t] = w * h;
        float s = fmaxf(w, h) * 0.5f;
        float x1 = cx - s, y1 = cy - s, x2 = cx + s, y2 = cy + s;
        sqx1[t] = x1; sqy1[t] = y1; sqx2[t] = x2; sqy2[t] = y2;
        sqar[t] = (x2 - x1) * (y2 - y1);
        scolF[t] = 0;
    }
    if (t == 127) scount = 0;
    __syncthreads();

    // ---- filter this block's 128 anchors ----
    int a = abase + t;
    const float* p = anc + (size_t)(img * NA + a) * 5;
    const float* q = ranc + (size_t)(img * NA + a) * 5;
    float s0 = fmaxf(p[2], p[3]) * 0.5f;
    float ax1 = p[0] - s0, ay1 = p[1] - s0, ax2 = p[0] + s0, ay2 = p[1] + s0;
    float aar = (ax2 - ax1) * (ay2 - ay1);
    float s1 = fmaxf(q[2], q[3]) * 0.5f;
    float rx1 = q[0] - s1, ry1 = q[1] - s1, rx2 = q[0] + s1, ry2 = q[1] + s1;
    float rar = (rx2 - rx1) * (ry2 - ry1);

    for (int j = 0; j < NM; j++) {
        float gx1 = sqx1[j], gy1 = sqy1[j], gx2 = sqx2[j], gy2 = sqy2[j], gar = sqar[j];
        float wx = fmaxf(fminf(ax2, gx2) - fmaxf(ax1, gx1), 0.0f);
        float wy = fmaxf(fminf(ay2, gy2) - fmaxf(ay1, gy1), 0.0f);
        float i0 = wx * wy;
        float d0 = aar + gar - i0 + 1e-8f;
        bool f0 = (i0 * 10.0f >= d0);
        if (fabsf(i0 * 10.0f - d0) < 1e-4f * d0) f0 = (i0 / d0 >= 0.1f);  // exact band
        wx = fmaxf(fminf(rx2, gx2) - fmaxf(rx1, gx1), 0.0f);
        wy = fmaxf(fminf(ry2, gy2) - fmaxf(ry1, gy1), 0.0f);
        float i1 = wx * wy;
        float d1 = rar + gar - i1 + 1e-8f;
        bool f1 = (i1 * 10.0f >= d1);
        if (fabsf(i1 * 10.0f - d1) < 1e-4f * d1) f1 = (i1 / d1 >= 0.1f);
        bool emit = f0 | f1;
        unsigned mask = __ballot_sync(0xffffffffu, emit);
        if (mask) {
            int leader = __ffs(mask) - 1;
            int rank = __popc(mask & ((1u << lane) - 1));
            int base = 0;
            if (lane == leader) base = atomicAdd(&scount, __popc(mask));
            base = __shfl_sync(0xffffffffu, base, leader);
            if (emit)
                slist[base + rank] = (t << 7) | (j << 2) | ((int)f1 << 1) | (int)f0;
        }
    }
    __syncthreads();

    // ---- clip this block's pairs ----
    int n = scount;
    const float lx[4] = {-0.5f, 0.5f, 0.5f, -0.5f};
    const float ly[4] = {-0.5f, -0.5f, 0.5f, 0.5f};
    for (int i = t; i < n; i += 128) {
        int code = slist[i];
        int f0 = code & 1, f1 = (code >> 1) & 1;
        int j = (code >> 2) & 31;
        int la = code >> 7;
        int ga = abase + la;
        float gar = sgar[j];
        float bf = 0.0f, af = 0.0f;
#pragma unroll
        for (int ph = 0; ph < 2; ph++) {
            if (!(ph ? f1 : f0)) continue;
            const float* pp = (ph ? ranc : anc) + (size_t)(img * NA + ga) * 5;
            float cx = pp[0], cy = pp[1], w = pp[2], h = pp[3];
            float th = pp[4] * (PI_F / 180.0f);
            float sn, cs;
            sincosf(th, &sn, &cs);
            float AX[4], AY[4], BX[4], BY[4];
#pragma unroll
            for (int k = 0; k < 4; k++) {
                float dx = w * lx[k], dy = h * ly[k];
                AX[k] = dx * cs - dy * sn;
                AY[k] = dx * sn + dy * cs;
                BX[k] = sgx[j][k] - cx;
                BY[k] = sgy[j][k] - cy;
            }
            float inter = quad_inter_area_f(AX, AY, BX, BY);
            float iou = inter / (w * h + gar - inter + 1e-8f);
            if (ph) af = iou; else bf = iou;
        }
        float md = fabsf(bf + 0.5f * af - fabsf(af - bf));
        g_md[img][ga][j] = md;
        atomicMax(&srow[la], spack(md, (unsigned)j));
        if (md > 0.0f) atomicMax(&scolF[j], spack(md, (unsigned)ga));
    }
    __syncthreads();

    g_rowkey[img][a] = srow[t];
    if (t < NM && scolF[t] > 0) atomicMax(&g_colkeyF[img][t], scolF[t]);
}

// ---------------- 2: colmax + interesting-anchor compaction ----------------
__global__ void __launch_bounds__(128) k_colmax() {
    int img = blockIdx.x >> 7;
    int a = (blockIdx.x & 127) * 128 + threadIdx.x;
    int lane = threadIdx.x & 31;
    __shared__ int sforce[NM];
    __shared__ ll scolp[NM];
    __shared__ int snp;
    if (threadIdx.x < NM) {
        float v; unsigned ix;
        sdec(g_colkeyF[img][threadIdx.x], v, ix);
        sforce[threadIdx.x] = (v < 0.5f) ? (int)ix : -1;
        scolp[threadIdx.x] = NEGK;
    }
    if (threadIdx.x == 127) snp = 0;
    __syncthreads();

    float iomax; unsigned jm;
    sdec(g_rowkey[img][a], iomax, jm);
    bool pos = (iomax >= 0.5f);
#pragma unroll
    for (int j = 0; j < NM; j++) pos |= (sforce[j] == a);
    if (pos) {
        const float4* mrow = (const float4*)g_md[img][a];
#pragma unroll
        for (int c = 0; c < 8; c++) {
            float4 m = mrow[c];
            atomicMax(&scolp[c * 4 + 0], spack(m.x, (unsigned)a));
            atomicMax(&scolp[c * 4 + 1], spack(m.y, (unsigned)a));
            atomicMax(&scolp[c * 4 + 2], spack(m.z, (unsigned)a));
            atomicMax(&scolp[c * 4 + 3], spack(m.w, (unsigned)a));
        }
    }
    bool emit = pos || (iomax >= 0.4f);
    unsigned mask = __ballot_sync(0xffffffffu, emit);
    if (mask) {
        int leader = __ffs(mask) - 1;
        int rank = __popc(mask & ((1u << lane) - 1));
        int base = 0;
        if (lane == leader) base = atomicAdd(&g_listCount, __popc(mask));
        base = __shfl_sync(0xffffffffu, base, leader);
        if (emit)
            g_list[base + rank] = a | (img << 14) | ((int)pos << 15) | ((int)jm << 16);
    }
    unsigned pmask = __ballot_sync(0xffffffffu, pos);
    if (lane == 0 && pmask) atomicAdd(&snp, __popc(pmask));
    __syncthreads();
    if (threadIdx.x < NM && scolp[threadIdx.x] != NEGK)
        atomicMax(&g_colkeyP[img][threadIdx.x], scolp[threadIdx.x]);
    if (threadIdx.x == 127 && snp) atomicAdd(&g_numpos[img], snp);
}

// ---------------- 3: loss = dense base sum + sparse corrections + finalize ----------
// Grid MUST be 240 blocks x 256 threads: phase A covers exactly
// 240 * 512 = 122880 float4 = NB*NA*NC floats. img0 = blocks [0,120).
__global__ void __launch_bounds__(256) k_loss(const float* __restrict__ cls,
                                              const float* __restrict__ reg,
                                              const float* __restrict__ anc,
                                              const float* __restrict__ ann,
                                              float* __restrict__ out) {
    int t = threadIdx.x;
    float cs0 = 0.0f, cs1 = 0.0f, rs0 = 0.0f, rs1 = 0.0f;

    // --- Phase A: dense coalesced base-term sum (2 float4 per thread) ---
    {
        const float4* c4 = (const float4*)cls;
        int b = blockIdx.x * 512 + t;
        float s = 0.0f;
#pragma unroll
        for (int k = 0; k < 2; k++) {
            float4 v = c4[b + k * 256];
            s += baseterm(v.x) + baseterm(v.y) + baseterm(v.z) + baseterm(v.w);
        }
        if (blockIdx.x < 120) cs0 += s; else cs1 += s;
    }

    // --- Phase B: corrections over compacted list ---
    int nitems = g_listCount;
    int i = blockIdx.x * 256 + t;
    if (i < nitems) {
        int code = g_list[i];
        int a = code & (NA - 1);
        int img = (code >> 14) & 1;
        int pos = (code >> 15) & 1;
        int jm = (code >> 16) & 31;
        const float* crow = cls + ((size_t)img * NA + a) * NC;
        float cc = 0.0f, rr = 0.0f;
        if (!pos) {
            // ignore band: tgt = -1 everywhere -> remove base contribution
            float s = 0.0f;
#pragma unroll
            for (int c = 0; c < NC; c++) s += baseterm(crow[c]);
            cc = -s;
        } else {
            float mw = -1e30f;
            const float4* mrow = (const float4*)g_md[img][a];
#pragma unroll
            for (int c = 0; c < 8; c++) {
                float4 m = mrow[c];
                float mv[4] = {m.x, m.y, m.z, m.w};
#pragma unroll
                for (int k = 0; k < 4; k++) {
                    int j = c * 4 + k;
                    float v; unsigned ix;
                    sdec(g_colkeyP[img][j], v, ix);
                    float md = mv[k];
                    bool pm = (md >= 0.5f) || ((int)ix == a);
                    float comp = pm ? (1.0f - v) : md;
                    mw = fmaxf(mw, comp + md);
                }
            }
            const float* gt = ann + (size_t)(img * NM + jm) * 6;
            int lab = (int)gt[5];
            float xl = fminf(fmaxf(crow[lab], 0.0001f), 1.0f - 0.0001f);
            float posterm = 0.25f * (1.0f - xl) * (1.0f - xl) * (-__logf(xl + 1e-6f)) * (mw + 1.0f);
            cc = posterm - baseterm(crow[lab]);
            const float* ap = anc + (size_t)(img * NA + a) * 5;
            const float* rg = reg + (size_t)(img * NA + a) * 5;
            float tv[5];
            tv[0] = (gt[0] - ap[0]) / ap[2];
            tv[1] = (gt[1] - ap[1]) / ap[3];
            tv[2] = __logf(fmaxf(gt[2], 1.0f) / ap[2]);
            tv[3] = __logf(fmaxf(gt[3], 1.0f) / ap[3]);
            tv[4] = __tanf(gt[4] * (PI_F / 180.0f)) - __tanf(ap[4] * (PI_F / 180.0f));
            const float BETA = (float)(1.0 / 9.0);
#pragma unroll
            for (int k = 0; k < 5; k++) {
                float diff = fabsf(rg[k] - tv[k]);
                float sl = (diff < BETA) ? (0.5f * diff * diff / BETA) : (diff - 0.5f * BETA);
                rr += sl * mw;
            }
        }
        if (img == 0) { cs0 += cc; rs0 += rr; } else { cs1 += cc; rs1 += rr; }
    }

    // --- block reduction ---
    cs0 = warp_sum_f(cs0); cs1 = warp_sum_f(cs1);
    rs0 = warp_sum_f(rs0); rs1 = warp_sum_f(rs1);
    __shared__ float sc0[8], sc1[8], sr0[8], sr1[8];
    int warp = t >> 5;
    if ((t & 31) == 0) { sc0[warp] = cs0; sc1[warp] = cs1; sr0[warp] = rs0; sr1[warp] = rs1; }
    __syncthreads();
    __shared__ bool lastf;
    if (t == 0) {
        double c0 = 0.0, c1 = 0.0, r0 = 0.0, r1 = 0.0;
#pragma unroll
        for (int k = 0; k < 8; k++) {
            c0 += (double)sc0[k]; c1 += (double)sc1[k];
            r0 += (double)sr0[k]; r1 += (double)sr1[k];
        }
        if (c0 != 0.0) atomicAdd(&g_cls_sum[0], c0);
        if (c1 != 0.0) atomicAdd(&g_cls_sum[1], c1);
        if (r0 != 0.0) atomicAdd(&g_reg_sum[0], r0);
        if (r1 != 0.0) atomicAdd(&g_reg_sum[1], r1);
        __threadfence();
        unsigned tk = atomicAdd(&g_ticket, 1u);
        lastf = (tk == (unsigned)(gridDim.x - 1));
    }
    __syncthreads();
    if (lastf) {
        if (t < NB * NM) {
            g_colkeyF[t >> 5][t & 31] = 0;
            g_colkeyP[t >> 5][t & 31] = NEGK;
        }
        if (t == 64) g_listCount = 0;
        if (t == 65) g_ticket = 0;
        if (t == 0) {
            double lc = 0.0, lr = 0.0;
#pragma unroll
            for (int i2 = 0; i2 < NB; i2++) {
                int np = g_numpos[i2];
                lc += g_cls_sum[i2] / fmax((double)np, 1.0);
                if (np > 0) lr += g_reg_sum[i2] / (double)(np * 5);
                g_cls_sum[i2] = 0.0; g_reg_sum[i2] = 0.0; g_numpos[i2] = 0;
            }
            out[0] = (float)(lc / (double)NB);
            out[1] = (float)(lr / (double)NB);
        }
    }
}

// ---------------- launcher ----------------
extern "C" void kernel_launch(void* const* d_in, const int* in_sizes, int n_in,
                              void* d_out, int out_size) {
    const float* cls  = (const float*)d_in[0];
    const float* reg  = (const float*)d_in[1];
    const float* anc  = (const float*)d_in[2];
    const float* ranc = (const float*)d_in[3];
    const float* ann  = (const float*)d_in[4];
    float* out = (float*)d_out;

    k_match<<<256, 128>>>(anc, ranc, ann);
    k_colmax<<<256, 128>>>();
    k_loss<<<240, 256>>>(cls, reg, anc, ann, out);
}

// round 7
// speedup vs baseline: 1.0922x; 1.0922x over previous
#include <cuda_runtime.h>
#include <math.h>
#include <stdint.h>

#define NB 2
#define NA 16384
#define NM 32
#define NC 15
#define PI_F 3.14159265358979323846f

typedef long long ll;

#define NEGK (-9223372036854775807ll - 1ll)
#define N4 NEGK, NEGK, NEGK, NEGK
#define N32 N4, N4, N4, N4, N4, N4, N4, N4

// ---------------- persistent scratch (state restored each run) ----------------
__device__ float  g_md[NB][NA][NM];                    // pair entries rewritten each run
__device__ ll     g_rowkey[NB][NA];                    // identity 0; reset by k_colmax
__device__ ll     g_colkeyF[NB][NM];                   // identity 0; reset by finalize
__device__ ll     g_colkeyP[NB][NM] = {{N32}, {N32}};  // identity NEGK; reset by finalize
__device__ int    g_pairs[NB * NA * NM];
__device__ int    g_pairCount;                         // reset by k_colmax
__device__ int    g_list[NB * NA];                     // interesting anchors
__device__ int    g_listCount;                         // reset by finalize
__device__ double g_cls_sum[NB];                       // reset by finalize
__device__ double g_reg_sum[NB];
__device__ int    g_numpos[NB];
__device__ unsigned g_ticket;                          // reset by finalize

// key = (float_bits(v) << 32) - idx  (v >= 0): max favors larger v, then smaller idx.
__device__ __forceinline__ ll spack(float v, unsigned idx) {
    return (ll)((unsigned long long)__float_as_uint(v) << 32) - (ll)idx;
}
__device__ __forceinline__ void sdec(ll k, float& v, unsigned& idx) {
    unsigned lo = (unsigned)(k & 0xFFFFFFFFll);
    idx = (unsigned)(-(int)lo);
    unsigned vb = (unsigned)(((unsigned long long)(k + (ll)idx)) >> 32);
    v = __uint_as_float(vb);
}

__device__ __forceinline__ float warp_sum_f(float v) {
#pragma unroll
    for (int off = 16; off > 0; off >>= 1) v += __shfl_xor_sync(0xffffffffu, v, off);
    return v;
}

// focal "background" term; used identically in phase A and corrections
__device__ __forceinline__ float baseterm(float xr) {
    float x = fminf(fmaxf(xr, 0.0001f), 1.0f - 0.0001f);
    return 0.75f * x * x * (-__logf(1.0f - x + 1e-6f));
}

// Sutherland-Hodgman on centered f32 coordinates.
__device__ float quad_inter_area_f(const float* ax, const float* ay,
                                   const float* bx, const float* by) {
    float px[10], py[10], qx[10], qy[10];
    int n = 4;
#pragma unroll
    for (int i = 0; i < 4; i++) { px[i] = ax[i]; py[i] = ay[i]; }
    for (int e = 0; e < 4; e++) {
        float x0 = bx[e], y0 = by[e];
        int e2 = (e + 1) & 3;
        float dx = bx[e2] - x0, dy = by[e2] - y0;
        int m = 0;
        float xprev = px[n - 1], yprev = py[n - 1];
        float dprev = dx * (yprev - y0) - dy * (xprev - x0);
        for (int i = 0; i < n; i++) {
            float xc = px[i], yc = py[i];
            float dc = dx * (yc - y0) - dy * (xc - x0);
            bool inc = (dc >= 0.0f), inp = (dprev >= 0.0f);
            if (inc != inp) {
                float t = dprev / (dprev - dc);
                if (m < 10) { qx[m] = xprev + t * (xc - xprev); qy[m] = yprev + t * (yc - yprev); m++; }
            }
            if (inc) { if (m < 10) { qx[m] = xc; qy[m] = yc; m++; } }
            dprev = dc; xprev = xc; yprev = yc;
        }
        n = m;
        if (n == 0) return 0.0f;
        for (int i = 0; i < n; i++) { px[i] = qx[i]; py[i] = qy[i]; }
    }
    if (n < 3) return 0.0f;
    float s = 0.0f;
    float xp = px[n - 1], yp = py[n - 1];
    for (int i = 0; i < n; i++) { s += xp * py[i] - px[i] * yp; xp = px[i]; yp = py[i]; }
    return 0.5f * fabsf(s);
}

// ---------------- 1: filter (global compacted pair list, balanced later) -------------
__global__ void __launch_bounds__(128) k_filter(const float* __restrict__ anc,
                                                const float* __restrict__ ranc,
                                                const float* __restrict__ ann) {
    int idx = blockIdx.x * 128 + threadIdx.x;  // [0, NB*NA)
    int lane = threadIdx.x & 31;
    int a = idx & (NA - 1);
    int img = idx >> 14;

    __shared__ float sx1[NM], sy1[NM], sx2[NM], sy2[NM], sar[NM];
    if (threadIdx.x < NM) {
        const float* g = ann + (size_t)(img * NM + threadIdx.x) * 6;
        float cx = g[0], cy = g[1], w = g[2], h = g[3];
        float s = fmaxf(w, h) * 0.5f;
        sx1[threadIdx.x] = cx - s; sy1[threadIdx.x] = cy - s;
        sx2[threadIdx.x] = cx + s; sy2[threadIdx.x] = cy + s;
        sar[threadIdx.x] = (2.0f * s) * (2.0f * s);
    }
    __syncthreads();

    const float* p = anc + (size_t)(img * NA + a) * 5;
    const float* q = ranc + (size_t)(img * NA + a) * 5;
    float s0 = fmaxf(p[2], p[3]) * 0.5f;
    float ax1 = p[0] - s0, ay1 = p[1] - s0, ax2 = p[0] + s0, ay2 = p[1] + s0;
    float aar = (ax2 - ax1) * (ay2 - ay1);
    float s1 = fmaxf(q[2], q[3]) * 0.5f;
    float rx1 = q[0] - s1, ry1 = q[1] - s1, rx2 = q[0] + s1, ry2 = q[1] + s1;
    float rar = (rx2 - rx1) * (ry2 - ry1);

    int m = 0;
    int codes[NM];
#pragma unroll 4
    for (int j = 0; j < NM; j++) {
        float gx1 = sx1[j], gy1 = sy1[j], gx2 = sx2[j], gy2 = sy2[j], gar = sar[j];
        float wx = fmaxf(fminf(ax2, gx2) - fmaxf(ax1, gx1), 0.0f);
        float wy = fmaxf(fminf(ay2, gy2) - fmaxf(ay1, gy1), 0.0f);
        float i0 = wx * wy;
        bool f0 = (i0 / (aar + gar - i0 + 1e-8f)) >= 0.1f;
        wx = fmaxf(fminf(rx2, gx2) - fmaxf(rx1, gx1), 0.0f);
        wy = fmaxf(fminf(ry2, gy2) - fmaxf(ry1, gy1), 0.0f);
        float i1 = wx * wy;
        bool f1 = (i1 / (rar + gar - i1 + 1e-8f)) >= 0.1f;
        if (f0 | f1)
            codes[m++] = (img << 21) | (a << 7) | (j << 2) | ((int)f1 << 1) | (int)f0;
    }
    int incl = m;
#pragma unroll
    for (int off = 1; off < 32; off <<= 1) {
        int n = __shfl_up_sync(0xffffffffu, incl, off);
        if (lane >= off) incl += n;
    }
    int total = __shfl_sync(0xffffffffu, incl, 31);
    int base = 0;
    if (lane == 0 && total > 0) base = atomicAdd(&g_pairCount, total);
    base = __shfl_sync(0xffffffffu, base, 0);
    int off0 = base + incl - m;
    for (int i = 0; i < m; i++) g_pairs[off0 + i] = codes[i];
}

// ---------------- 2: heavy (grid-stride clip; balanced across all SMs) --------------
__global__ void __launch_bounds__(256) k_heavy(const float* __restrict__ anc,
                                               const float* __restrict__ ranc,
                                               const float* __restrict__ ann) {
    __shared__ float sgx[NB * NM][4], sgy[NB * NM][4];
    __shared__ float sgar[NB * NM];
    __shared__ ll scol[NB * NM];
    int t = threadIdx.x;
    if (t < NB * NM) {
        int img = t >> 5, j = t & 31;
        const float* g = ann + (size_t)(img * NM + j) * 6;
        float cx = g[0], cy = g[1], w = g[2], h = g[3];
        float th = g[4] * (PI_F / 180.0f);
        float sn, cs;
        sincosf(th, &sn, &cs);
        const float lx[4] = {-0.5f, 0.5f, 0.5f, -0.5f};
        const float ly[4] = {-0.5f, -0.5f, 0.5f, 0.5f};
#pragma unroll
        for (int k = 0; k < 4; k++) {
            float dx = w * lx[k], dy = h * ly[k];
            sgx[t][k] = cx + dx * cs - dy * sn;
            sgy[t][k] = cy + dx * sn + dy * cs;
        }
        sgar[t] = w * h;
        scol[t] = 0;
    }
    __syncthreads();

    int total = g_pairCount;
    const float lx[4] = {-0.5f, 0.5f, 0.5f, -0.5f};
    const float ly[4] = {-0.5f, -0.5f, 0.5f, 0.5f};
    for (int idx = blockIdx.x * blockDim.x + threadIdx.x; idx < total;
         idx += gridDim.x * blockDim.x) {
        int code = g_pairs[idx];
        int f0 = code & 1, f1 = (code >> 1) & 1;
        int j = (code >> 2) & 31;
        int a = (code >> 7) & (NA - 1);
        int img = (code >> 21) & 1;
        int gj = img * 32 + j;
        float gar = sgar[gj];
        float bf = 0.0f, af = 0.0f;
#pragma unroll
        for (int ph = 0; ph < 2; ph++) {
            if (!(ph ? f1 : f0)) continue;
            const float* pp = (ph ? ranc : anc) + (size_t)(img * NA + a) * 5;
            float cx = pp[0], cy = pp[1], w = pp[2], h = pp[3];
            float th = pp[4] * (PI_F / 180.0f);
            float sn, cs;
            sincosf(th, &sn, &cs);
            float AX[4], AY[4], BX[4], BY[4];
#pragma unroll
            for (int k = 0; k < 4; k++) {
                float dx = w * lx[k], dy = h * ly[k];
                AX[k] = dx * cs - dy * sn;
                AY[k] = dx * sn + dy * cs;
                BX[k] = sgx[gj][k] - cx;
                BY[k] = sgy[gj][k] - cy;
            }
            float inter = quad_inter_area_f(AX, AY, BX, BY);
            float iou = inter / (w * h + gar - inter + 1e-8f);
            if (ph) af = iou; else bf = iou;
        }
        float md = fabsf(bf + 0.5f * af - fabsf(af - bf));
        g_md[img][a][j] = md;
        atomicMax(&g_rowkey[img][a], spack(md, (unsigned)j));
        if (md > 0.0f) atomicMax(&scol[gj], spack(md, (unsigned)a));
    }
    __syncthreads();
    if (t < NB * NM) {
        if (scol[t] > 0) atomicMax(&g_colkeyF[t >> 5][t & 31], scol[t]);
    }
}

// ---------------- 3: colmax + interesting-anchor compaction (+ rowkey reset) ---------
__global__ void __launch_bounds__(128) k_colmax() {
    int img = blockIdx.x >> 7;
    int a = (blockIdx.x & 127) * 128 + threadIdx.x;
    int lane = threadIdx.x & 31;
    __shared__ int sforce[NM];
    __shared__ ll scolp[NM];
    __shared__ int snp;
    if (threadIdx.x < NM) {
        float v; unsigned ix;
        sdec(g_colkeyF[img][threadIdx.x], v, ix);
        sforce[threadIdx.x] = (v < 0.5f) ? (int)ix : -1;
        scolp[threadIdx.x] = NEGK;
    }
    if (threadIdx.x == 127) snp = 0;
    if (blockIdx.x == 0 && threadIdx.x == 126) g_pairCount = 0;  // consumed by k_heavy
    __syncthreads();

    ll rk = g_rowkey[img][a];
    if (rk != 0) g_rowkey[img][a] = 0;  // restore identity for next replay
    float iomax; unsigned jm;
    sdec(rk, iomax, jm);
    bool pos = (iomax >= 0.5f);
#pragma unroll
    for (int j = 0; j < NM; j++) pos |= (sforce[j] == a);
    if (pos) {
        const float4* mrow = (const float4*)g_md[img][a];
#pragma unroll
        for (int c = 0; c < 8; c++) {
            float4 m = mrow[c];
            atomicMax(&scolp[c * 4 + 0], spack(m.x, (unsigned)a));
            atomicMax(&scolp[c * 4 + 1], spack(m.y, (unsigned)a));
            atomicMax(&scolp[c * 4 + 2], spack(m.z, (unsigned)a));
            atomicMax(&scolp[c * 4 + 3], spack(m.w, (unsigned)a));
        }
    }
    bool emit = pos || (iomax >= 0.4f);
    unsigned mask = __ballot_sync(0xffffffffu, emit);
    if (mask) {
        int leader = __ffs(mask) - 1;
        int rank = __popc(mask & ((1u << lane) - 1));
        int base = 0;
        if (lane == leader) base = atomicAdd(&g_listCount, __popc(mask));
        base = __shfl_sync(0xffffffffu, base, leader);
        if (emit)
            g_list[base + rank] = a | (img << 14) | ((int)pos << 15) | ((int)jm << 16);
    }
    unsigned pmask = __ballot_sync(0xffffffffu, pos);
    if (lane == 0 && pmask) atomicAdd(&snp, __popc(pmask));
    __syncthreads();
    if (threadIdx.x < NM && scolp[threadIdx.x] != NEGK)
        atomicMax(&g_colkeyP[img][threadIdx.x], scolp[threadIdx.x]);
    if (threadIdx.x == 127 && snp) atomicAdd(&g_numpos[img], snp);
}

// ---------------- 4: loss = dense base sum + sparse corrections + finalize ----------
// Grid MUST be 240 blocks x 256 threads: phase A covers exactly
// 240 * 512 = 122880 float4 = NB*NA*NC floats. img0 = blocks [0,120).
__global__ void __launch_bounds__(256) k_loss(const float* __restrict__ cls,
                                              const float* __restrict__ reg,
                                              const float* __restrict__ anc,
                                              const float* __restrict__ ann,
                                              float* __restrict__ out) {
    int t = threadIdx.x;
    float cs0 = 0.0f, cs1 = 0.0f, rs0 = 0.0f, rs1 = 0.0f;

    // --- Phase A: dense coalesced base-term sum (2 float4 per thread) ---
    {
        const float4* c4 = (const float4*)cls;
        int b = blockIdx.x * 512 + t;
        float s = 0.0f;
#pragma unroll
        for (int k = 0; k < 2; k++) {
            float4 v = c4[b + k * 256];
            s += baseterm(v.x) + baseterm(v.y) + baseterm(v.z) + baseterm(v.w);
        }
        if (blockIdx.x < 120) cs0 += s; else cs1 += s;
    }

    // --- Phase B: corrections over compacted list ---
    int nitems = g_listCount;
    int i = blockIdx.x * 256 + t;
    if (i < nitems) {
        int code = g_list[i];
        int a = code & (NA - 1);
        int img = (code >> 14) & 1;
        int pos = (code >> 15) & 1;
        int jm = (code >> 16) & 31;
        const float* crow = cls + ((size_t)img * NA + a) * NC;
        float cc = 0.0f, rr = 0.0f;
        if (!pos) {
            float s = 0.0f;
#pragma unroll
            for (int c = 0; c < NC; c++) s += baseterm(crow[c]);
            cc = -s;
        } else {
            float mw = -1e30f;
            const float4* mrow = (const float4*)g_md[img][a];
#pragma unroll
            for (int c = 0; c < 8; c++) {
                float4 m = mrow[c];
                float mv[4] = {m.x, m.y, m.z, m.w};
#pragma unroll
                for (int k = 0; k < 4; k++) {
                    int j = c * 4 + k;
                    float v; unsigned ix;
                    sdec(g_colkeyP[img][j], v, ix);
                    float md = mv[k];
                    bool pm = (md >= 0.5f) || ((int)ix == a);
                    float comp = pm ? (1.0f - v) : md;
                    mw = fmaxf(mw, comp + md);
                }
            }
            const float* gt = ann + (size_t)(img * NM + jm) * 6;
            int lab = (int)gt[5];
            float xl = fminf(fmaxf(crow[lab], 0.0001f), 1.0f - 0.0001f);
            float posterm = 0.25f * (1.0f - xl) * (1.0f - xl) * (-__logf(xl + 1e-6f)) * (mw + 1.0f);
            cc = posterm - baseterm(crow[lab]);
            const float* ap = anc + (size_t)(img * NA + a) * 5;
            const float* rg = reg + (size_t)(img * NA + a) * 5;
            float tv[5];
            tv[0] = (gt[0] - ap[0]) / ap[2];
            tv[1] = (gt[1] - ap[1]) / ap[3];
            tv[2] = __logf(fmaxf(gt[2], 1.0f) / ap[2]);
            tv[3] = __logf(fmaxf(gt[3], 1.0f) / ap[3]);
            tv[4] = __tanf(gt[4] * (PI_F / 180.0f)) - __tanf(ap[4] * (PI_F / 180.0f));
            const float BETA = (float)(1.0 / 9.0);
#pragma unroll
            for (int k = 0; k < 5; k++) {
                float diff = fabsf(rg[k] - tv[k]);
                float sl = (diff < BETA) ? (0.5f * diff * diff / BETA) : (diff - 0.5f * BETA);
                rr += sl * mw;
            }
        }
        if (img == 0) { cs0 += cc; rs0 += rr; } else { cs1 += cc; rs1 += rr; }
    }

    // --- block reduction + fused finalize ---
    cs0 = warp_sum_f(cs0); cs1 = warp_sum_f(cs1);
    rs0 = warp_sum_f(rs0); rs1 = warp_sum_f(rs1);
    __shared__ float sc0[8], sc1[8], sr0[8], sr1[8];
    int warp = t >> 5;
    if ((t & 31) == 0) { sc0[warp] = cs0; sc1[warp] = cs1; sr0[warp] = rs0; sr1[warp] = rs1; }
    __syncthreads();
    __shared__ bool lastf;
    if (t == 0) {
        double c0 = 0.0, c1 = 0.0, r0 = 0.0, r1 = 0.0;
#pragma unroll
        for (int k = 0; k < 8; k++) {
            c0 += (double)sc0[k]; c1 += (double)sc1[k];
            r0 += (double)sr0[k]; r1 += (double)sr1[k];
        }
        if (c0 != 0.0) atomicAdd(&g_cls_sum[0], c0);
        if (c1 != 0.0) atomicAdd(&g_cls_sum[1], c1);
        if (r0 != 0.0) atomicAdd(&g_reg_sum[0], r0);
        if (r1 != 0.0) atomicAdd(&g_reg_sum[1], r1);
        __threadfence();
        unsigned tk = atomicAdd(&g_ticket, 1u);
        lastf = (tk == (unsigned)(gridDim.x - 1));
    }
    __syncthreads();
    if (lastf) {
        if (t < NB * NM) {
            g_colkeyF[t >> 5][t & 31] = 0;
            g_colkeyP[t >> 5][t & 31] = NEGK;
        }
        if (t == 64) g_listCount = 0;
        if (t == 65) g_ticket = 0;
        if (t == 0) {
            double lc = 0.0, lr = 0.0;
#pragma unroll
            for (int i2 = 0; i2 < NB; i2++) {
                int np = g_numpos[i2];
                lc += g_cls_sum[i2] / fmax((double)np, 1.0);
                if (np > 0) lr += g_reg_sum[i2] / (double)(np * 5);
                g_cls_sum[i2] = 0.0; g_reg_sum[i2] = 0.0; g_numpos[i2] = 0;
            }
            out[0] = (float)(lc / (double)NB);
            out[1] = (float)(lr / (double)NB);
        }
    }
}

// ---------------- launcher ----------------
extern "C" void kernel_launch(void* const* d_in, const int* in_sizes, int n_in,
                              void* d_out, int out_size) {
    const float* cls  = (const float*)d_in[0];
    const float* reg  = (const float*)d_in[1];
    const float* anc  = (const float*)d_in[2];
    const float* ranc = (const float*)d_in[3];
    const float* ann  = (const float*)d_in[4];
    float* out = (float*)d_out;

    k_filter<<<(NB * NA) / 128, 128>>>(anc, ranc, ann);
    k_heavy<<<148, 256>>>(anc, ranc, ann);
    k_colmax<<<256, 128>>>();
    k_loss<<<240, 256>>>(cls, reg, anc, ann, out);
}

// round 8
// speedup vs baseline: 1.1147x; 1.0206x over previous
#include <cuda_runtime.h>
#include <math.h>
#include <stdint.h>

#define NB 2
#define NA 16384
#define NM 32
#define NC 15
#define PI_F 3.14159265358979323846f
#define NBLK 148
#define NTHR 256
#define GSZ (NBLK * NTHR)

typedef long long ll;

#define NEGK (-9223372036854775807ll - 1ll)
#define N4 NEGK, NEGK, NEGK, NEGK
#define N32 N4, N4, N4, N4, N4, N4, N4, N4

// ---------------- persistent scratch (zero-init; finalize restores all state) --------
__device__ float  g_md[NB][NA][NM];                    // pair entries rewritten each run
__device__ ll     g_rowkey[NB][NA];                    // identity 0; reset in phase 3
__device__ ll     g_colkeyF[NB][NM];                   // identity 0; reset by finalize
__device__ ll     g_colkeyP[NB][NM] = {{N32}, {N32}};  // identity NEGK; reset by finalize
__device__ int    g_pairs[NB * NA * NM];
__device__ int    g_pairCount;                         // reset in phase 3
__device__ int    g_list[NB * NA];
__device__ int    g_listCount;                         // reset by finalize
__device__ double g_cls_sum[NB];                       // reset by finalize
__device__ double g_reg_sum[NB];
__device__ int    g_numpos[NB];
__device__ unsigned g_ticket;                          // reset by finalize
__device__ unsigned g_barCnt[3];                       // reset by finalize

// key = (float_bits(v) << 32) - idx  (v >= 0): max favors larger v, then smaller idx.
__device__ __forceinline__ ll spack(float v, unsigned idx) {
    return (ll)((unsigned long long)__float_as_uint(v) << 32) - (ll)idx;
}
__device__ __forceinline__ void sdec(ll k, float& v, unsigned& idx) {
    unsigned lo = (unsigned)(k & 0xFFFFFFFFll);
    idx = (unsigned)(-(int)lo);
    unsigned vb = (unsigned)(((unsigned long long)(k + (ll)idx)) >> 32);
    v = __uint_as_float(vb);
}

__device__ __forceinline__ float warp_sum_f(float v) {
#pragma unroll
    for (int off = 16; off > 0; off >>= 1) v += __shfl_xor_sync(0xffffffffu, v, off);
    return v;
}

__device__ __forceinline__ float baseterm(float xr) {
    float x = fminf(fmaxf(xr, 0.0001f), 1.0f - 0.0001f);
    return 0.75f * x * x * (-__logf(1.0f - x + 1e-6f));
}

// grid barrier: per-instance counter, used once per run, reset by finalize.
__device__ __forceinline__ void grid_barrier(int k) {
    __syncthreads();
    if (threadIdx.x == 0) {
        __threadfence();
        atomicAdd(&g_barCnt[k], 1u);
        while (*(volatile unsigned*)&g_barCnt[k] < (unsigned)NBLK) { __nanosleep(32); }
        __threadfence();
    }
    __syncthreads();
}

// Sutherland-Hodgman on centered f32 coordinates.
__device__ float quad_inter_area_f(const float* ax, const float* ay,
                                   const float* bx, const float* by) {
    float px[10], py[10], qx[10], qy[10];
    int n = 4;
#pragma unroll
    for (int i = 0; i < 4; i++) { px[i] = ax[i]; py[i] = ay[i]; }
    for (int e = 0; e < 4; e++) {
        float x0 = bx[e], y0 = by[e];
        int e2 = (e + 1) & 3;
        float dx = bx[e2] - x0, dy = by[e2] - y0;
        int m = 0;
        float xprev = px[n - 1], yprev = py[n - 1];
        float dprev = dx * (yprev - y0) - dy * (xprev - x0);
        for (int i = 0; i < n; i++) {
            float xc = px[i], yc = py[i];
            float dc = dx * (yc - y0) - dy * (xc - x0);
            bool inc = (dc >= 0.0f), inp = (dprev >= 0.0f);
            if (inc != inp) {
                float t = dprev / (dprev - dc);
                if (m < 10) { qx[m] = xprev + t * (xc - xprev); qy[m] = yprev + t * (yc - yprev); m++; }
            }
            if (inc) { if (m < 10) { qx[m] = xc; qy[m] = yc; m++; } }
            dprev = dc; xprev = xc; yprev = yc;
        }
        n = m;
        if (n == 0) return 0.0f;
        for (int i = 0; i < n; i++) { px[i] = qx[i]; py[i] = qy[i]; }
    }
    if (n < 3) return 0.0f;
    float s = 0.0f;
    float xp = px[n - 1], yp = py[n - 1];
    for (int i = 0; i < n; i++) { s += xp * py[i] - px[i] * yp; xp = px[i]; yp = py[i]; }
    return 0.5f * fabsf(s);
}

// ================ the single persistent kernel ================
__global__ void __launch_bounds__(NTHR, 1) k_all(const float* __restrict__ cls,
                                                 const float* __restrict__ reg,
                                                 const float* __restrict__ anc,
                                                 const float* __restrict__ ranc,
                                                 const float* __restrict__ ann,
                                                 float* __restrict__ out) {
    int tid = threadIdx.x;
    int lane = tid & 31;
    int gtid = blockIdx.x * NTHR + tid;

    // gt data for BOTH images (64 boxes), per block
    __shared__ float sgx[NB * NM][4], sgy[NB * NM][4], sgar[NB * NM];
    __shared__ float sqx1[NB * NM], sqy1[NB * NM], sqx2[NB * NM], sqy2[NB * NM], sqar[NB * NM];
    __shared__ ll scol[NB * NM];

    if (tid < NB * NM) {
        int img = tid >> 5, j = tid & 31;
        const float* g = ann + (size_t)(img * NM + j) * 6;
        float cx = g[0], cy = g[1], w = g[2], h = g[3];
        float th = g[4] * (PI_F / 180.0f);
        float sn, cs;
        sincosf(th, &sn, &cs);
        const float lx[4] = {-0.5f, 0.5f, 0.5f, -0.5f};
        const float ly[4] = {-0.5f, -0.5f, 0.5f, 0.5f};
#pragma unroll
        for (int k = 0; k < 4; k++) {
            float dx = w * lx[k], dy = h * ly[k];
            sgx[tid][k] = cx + dx * cs - dy * sn;
            sgy[tid][k] = cy + dx * sn + dy * cs;
        }
        sgar[tid] = w * h;
        float s = fmaxf(w, h) * 0.5f;
        sqx1[tid] = cx - s; sqy1[tid] = cy - s;
        sqx2[tid] = cx + s; sqy2[tid] = cy + s;
        sqar[tid] = (2.0f * s) * (2.0f * s);
        scol[tid] = 0;
    }
    __syncthreads();

    // ---------------- Phase 1: filter (one anchor per thread) ----------------
    if (gtid < NB * NA) {
        int a = gtid & (NA - 1);
        int img = gtid >> 14;
        const float* p = anc + (size_t)gtid * 5;
        const float* q = ranc + (size_t)gtid * 5;
        float s0 = fmaxf(p[2], p[3]) * 0.5f;
        float ax1 = p[0] - s0, ay1 = p[1] - s0, ax2 = p[0] + s0, ay2 = p[1] + s0;
        float aar = (ax2 - ax1) * (ay2 - ay1);
        float s1 = fmaxf(q[2], q[3]) * 0.5f;
        float rx1 = q[0] - s1, ry1 = q[1] - s1, rx2 = q[0] + s1, ry2 = q[1] + s1;
        float rar = (rx2 - rx1) * (ry2 - ry1);
        int jb = img << 5;

        int m = 0;
        int codes[NM];
#pragma unroll 4
        for (int j = 0; j < NM; j++) {
            float gx1 = sqx1[jb + j], gy1 = sqy1[jb + j];
            float gx2 = sqx2[jb + j], gy2 = sqy2[jb + j], gar = sqar[jb + j];
            float wx = fmaxf(fminf(ax2, gx2) - fmaxf(ax1, gx1), 0.0f);
            float wy = fmaxf(fminf(ay2, gy2) - fmaxf(ay1, gy1), 0.0f);
            float i0 = wx * wy;
            bool f0 = (i0 / (aar + gar - i0 + 1e-8f)) >= 0.1f;
            wx = fmaxf(fminf(rx2, gx2) - fmaxf(rx1, gx1), 0.0f);
            wy = fmaxf(fminf(ry2, gy2) - fmaxf(ry1, gy1), 0.0f);
            float i1 = wx * wy;
            bool f1 = (i1 / (rar + gar - i1 + 1e-8f)) >= 0.1f;
            if (f0 | f1)
                codes[m++] = (img << 21) | (a << 7) | (j << 2) | ((int)f1 << 1) | (int)f0;
        }
        int incl = m;
#pragma unroll
        for (int off = 1; off < 32; off <<= 1) {
            int nn = __shfl_up_sync(0xffffffffu, incl, off);
            if (lane >= off) incl += nn;
        }
        int total = __shfl_sync(0xffffffffu, incl, 31);
        int base = 0;
        if (lane == 0 && total > 0) base = atomicAdd(&g_pairCount, total);
        base = __shfl_sync(0xffffffffu, base, 0);
        int off0 = base + incl - m;
        for (int i = 0; i < m; i++) g_pairs[off0 + i] = codes[i];
    }

    grid_barrier(0);

    // ---------------- Phase 2: heavy (grid-stride clip) ----------------
    {
        int total = g_pairCount;
        const float lx[4] = {-0.5f, 0.5f, 0.5f, -0.5f};
        const float ly[4] = {-0.5f, -0.5f, 0.5f, 0.5f};
        for (int idx = gtid; idx < total; idx += GSZ) {
            int code = g_pairs[idx];
            int f0 = code & 1, f1 = (code >> 1) & 1;
            int j = (code >> 2) & 31;
            int a = (code >> 7) & (NA - 1);
            int img = (code >> 21) & 1;
            int gj = (img << 5) + j;
            float gar = sgar[gj];
            float bf = 0.0f, af = 0.0f;
#pragma unroll
            for (int ph = 0; ph < 2; ph++) {
                if (!(ph ? f1 : f0)) continue;
                const float* pp = (ph ? ranc : anc) + (size_t)(img * NA + a) * 5;
                float cx = pp[0], cy = pp[1], w = pp[2], h = pp[3];
                float th = pp[4] * (PI_F / 180.0f);
                float sn, cs;
                sincosf(th, &sn, &cs);
                float AX[4], AY[4], BX[4], BY[4];
#pragma unroll
                for (int k = 0; k < 4; k++) {
                    float dx = w * lx[k], dy = h * ly[k];
                    AX[k] = dx * cs - dy * sn;
                    AY[k] = dx * sn + dy * cs;
                    BX[k] = sgx[gj][k] - cx;
                    BY[k] = sgy[gj][k] - cy;
                }
                float inter = quad_inter_area_f(AX, AY, BX, BY);
                float iou = inter / (w * h + gar - inter + 1e-8f);
                if (ph) af = iou; else bf = iou;
            }
            float md = fabsf(bf + 0.5f * af - fabsf(af - bf));
            g_md[img][a][j] = md;
            atomicMax(&g_rowkey[img][a], spack(md, (unsigned)j));
            if (md > 0.0f) atomicMax(&scol[gj], spack(md, (unsigned)a));
        }
        __syncthreads();
        if (tid < NB * NM && scol[tid] > 0)
            atomicMax(&g_colkeyF[tid >> 5][tid & 31], scol[tid]);
    }

    grid_barrier(1);

    // ---------------- Phase 3: colmax + force + compaction ----------------
    __shared__ int sforce[NB * NM];
    __shared__ ll scolp[NB * NM];
    __shared__ int snp[NB];
    if (tid < NB * NM) {
        float v; unsigned ix;
        sdec(g_colkeyF[tid >> 5][tid & 31], v, ix);
        sforce[tid] = (v < 0.5f) ? (int)ix : -1;
        scolp[tid] = NEGK;
    }
    if (tid == 128) { snp[0] = 0; snp[1] = 0; }
    if (gtid == GSZ - 1) g_pairCount = 0;  // consumed; reset for next replay
    __syncthreads();

    if (gtid < NB * NA) {
        int a = gtid & (NA - 1);
        int img = gtid >> 14;
        int jb = img << 5;
        ll rk = g_rowkey[img][a];
        if (rk != 0) g_rowkey[img][a] = 0;  // restore identity
        float iomax; unsigned jm;
        sdec(rk, iomax, jm);
        bool pos = (iomax >= 0.5f);
#pragma unroll
        for (int j = 0; j < NM; j++) pos |= (sforce[jb + j] == a);
        if (pos) {
            const float4* mrow = (const float4*)g_md[img][a];
#pragma unroll
            for (int c = 0; c < 8; c++) {
                float4 m = mrow[c];
                atomicMax(&scolp[jb + c * 4 + 0], spack(m.x, (unsigned)a));
                atomicMax(&scolp[jb + c * 4 + 1], spack(m.y, (unsigned)a));
                atomicMax(&scolp[jb + c * 4 + 2], spack(m.z, (unsigned)a));
                atomicMax(&scolp[jb + c * 4 + 3], spack(m.w, (unsigned)a));
            }
        }
        bool emit = pos || (iomax >= 0.4f);
        unsigned mask = __ballot_sync(0xffffffffu, emit);
        if (mask) {
            int leader = __ffs(mask) - 1;
            int rank = __popc(mask & ((1u << lane) - 1));
            int base = 0;
            if (lane == leader) base = atomicAdd(&g_listCount, __popc(mask));
            base = __shfl_sync(0xffffffffu, base, leader);
            if (emit)
                g_list[base + rank] = a | (img << 14) | ((int)pos << 15) | ((int)jm << 16);
        }
        unsigned pmask = __ballot_sync(0xffffffffu, pos);
        if (lane == 0 && pmask) atomicAdd(&snp[img], __popc(pmask));  // warp img-uniform
    }
    __syncthreads();
    if (tid < NB * NM && scolp[tid] != NEGK)
        atomicMax(&g_colkeyP[tid >> 5][tid & 31], scolp[tid]);
    if (tid == 128 && snp[0]) atomicAdd(&g_numpos[0], snp[0]);
    if (tid == 129 && snp[1]) atomicAdd(&g_numpos[1], snp[1]);

    grid_barrier(2);

    // ---------------- Phase 4: dense base sum + sparse corrections ----------------
    float cs0 = 0.0f, cs1 = 0.0f, rs0 = 0.0f, rs1 = 0.0f;
    {
        const float4* c4 = (const float4*)cls;
        const int HALF = NA * NC / 4;  // 61440 float4 per image
        for (int i = gtid; i < 2 * HALF; i += GSZ) {
            float4 v = c4[i];
            float s = baseterm(v.x) + baseterm(v.y) + baseterm(v.z) + baseterm(v.w);
            if (i < HALF) cs0 += s; else cs1 += s;
        }
    }
    {
        int nitems = g_listCount;
        for (int i = gtid; i < nitems; i += GSZ) {
            int code = g_list[i];
            int a = code & (NA - 1);
            int img = (code >> 14) & 1;
            int pos = (code >> 15) & 1;
            int jm = (code >> 16) & 31;
            const float* crow = cls + ((size_t)img * NA + a) * NC;
            float cc = 0.0f, rr = 0.0f;
            if (!pos) {
                float s = 0.0f;
#pragma unroll
                for (int c = 0; c < NC; c++) s += baseterm(crow[c]);
                cc = -s;
            } else {
                float mw = -1e30f;
                const float4* mrow = (const float4*)g_md[img][a];
#pragma unroll
                for (int c = 0; c < 8; c++) {
                    float4 m = mrow[c];
                    float mv[4] = {m.x, m.y, m.z, m.w};
#pragma unroll
                    for (int k = 0; k < 4; k++) {
                        int j = c * 4 + k;
                        float v; unsigned ix;
                        sdec(g_colkeyP[img][j], v, ix);
                        float md = mv[k];
                        bool pm = (md >= 0.5f) || ((int)ix == a);
                        float comp = pm ? (1.0f - v) : md;
                        mw = fmaxf(mw, comp + md);
                    }
                }
                const float* gt = ann + (size_t)(img * NM + jm) * 6;
                int lab = (int)gt[5];
                float xl = fminf(fmaxf(crow[lab], 0.0001f), 1.0f - 0.0001f);
                float posterm = 0.25f * (1.0f - xl) * (1.0f - xl) * (-__logf(xl + 1e-6f)) * (mw + 1.0f);
                cc = posterm - baseterm(crow[lab]);
                const float* ap = anc + (size_t)(img * NA + a) * 5;
                const float* rg = reg + (size_t)(img * NA + a) * 5;
                float tv[5];
                tv[0] = (gt[0] - ap[0]) / ap[2];
                tv[1] = (gt[1] - ap[1]) / ap[3];
                tv[2] = __logf(fmaxf(gt[2], 1.0f) / ap[2]);
                tv[3] = __logf(fmaxf(gt[3], 1.0f) / ap[3]);
                tv[4] = __tanf(gt[4] * (PI_F / 180.0f)) - __tanf(ap[4] * (PI_F / 180.0f));
                const float BETA = (float)(1.0 / 9.0);
#pragma unroll
                for (int k = 0; k < 5; k++) {
                    float diff = fabsf(rg[k] - tv[k]);
                    float sl = (diff < BETA) ? (0.5f * diff * diff / BETA) : (diff - 0.5f * BETA);
                    rr += sl * mw;
                }
            }
            if (img == 0) { cs0 += cc; rs0 += rr; } else { cs1 += cc; rs1 += rr; }
        }
    }

    // ---------------- block reduction + ticket finalize ----------------
    cs0 = warp_sum_f(cs0); cs1 = warp_sum_f(cs1);
    rs0 = warp_sum_f(rs0); rs1 = warp_sum_f(rs1);
    __shared__ float sc0[8], sc1[8], sr0[8], sr1[8];
    int warp = tid >> 5;
    if (lane == 0) { sc0[warp] = cs0; sc1[warp] = cs1; sr0[warp] = rs0; sr1[warp] = rs1; }
    __syncthreads();
    __shared__ bool lastf;
    if (tid == 0) {
        double c0 = 0.0, c1 = 0.0, r0 = 0.0, r1 = 0.0;
#pragma unroll
        for (int k = 0; k < 8; k++) {
            c0 += (double)sc0[k]; c1 += (double)sc1[k];
            r0 += (double)sr0[k]; r1 += (double)sr1[k];
        }
        if (c0 != 0.0) atomicAdd(&g_cls_sum[0], c0);
        if (c1 != 0.0) atomicAdd(&g_cls_sum[1], c1);
        if (r0 != 0.0) atomicAdd(&g_reg_sum[0], r0);
        if (r1 != 0.0) atomicAdd(&g_reg_sum[1], r1);
        __threadfence();
        unsigned tk = atomicAdd(&g_ticket, 1u);
        lastf = (tk == (unsigned)(NBLK - 1));
    }
    __syncthreads();
    if (lastf) {
        if (tid < NB * NM) {
            g_colkeyF[tid >> 5][tid & 31] = 0;
            g_colkeyP[tid >> 5][tid & 31] = NEGK;
        }
        if (tid == 64) g_listCount = 0;
        if (tid == 65) g_ticket = 0;
        if (tid == 66) { g_barCnt[0] = 0; g_barCnt[1] = 0; g_barCnt[2] = 0; }
        if (tid == 0) {
            double lc = 0.0, lr = 0.0;
#pragma unroll
            for (int i2 = 0; i2 < NB; i2++) {
                int np = g_numpos[i2];
                lc += g_cls_sum[i2] / fmax((double)np, 1.0);
                if (np > 0) lr += g_reg_sum[i2] / (double)(np * 5);
                g_cls_sum[i2] = 0.0; g_reg_sum[i2] = 0.0; g_numpos[i2] = 0;
            }
            out[0] = (float)(lc / (double)NB);
            out[1] = (float)(lr / (double)NB);
        }
    }
}

// ---------------- launcher: ONE kernel ----------------
extern "C" void kernel_launch(void* const* d_in, const int* in_sizes, int n_in,
                              void* d_out, int out_size) {
    const float* cls  = (const float*)d_in[0];
    const float* reg  = (const float*)d_in[1];
    const float* anc  = (const float*)d_in[2];
    const float* ranc = (const float*)d_in[3];
    const float* ann  = (const float*)d_in[4];
    float* out = (float*)d_out;

    k_all<<<NBLK, NTHR>>>(cls, reg, anc, ranc, ann, out);
}